// round 1
// baseline (speedup 1.0000x reference)
#include <cuda_runtime.h>

#define PB   128          // pasted box size
#define PHW  256          // patch resolution
#define HW   1024         // image H = W
#define BIMG 8            // batch
#define NPER 16           // boxes per image
#define NB   128          // total boxes = BIMG*NPER

// Scratch (device globals: no allocation allowed in kernel_launch)
__device__ float g_small[PB * PB * 3];   // downsampled patch 128x128x3
__device__ float g_acc[PB * PB * 3];     // summed inverse-transformed gradients

// ---------------------------------------------------------------------------
// K1: antialiased bilinear downsample patch 256x256x3 -> 128x128x3
// JAX resize (antialias=True, scale=0.5): taps at 2i-1..2i+2 with triangle
// weights {0.25,0.75,0.75,0.25}, renormalized per-dim at edges.
// ---------------------------------------------------------------------------
__global__ void k_downsample(const float* __restrict__ patch) {
    int t = blockIdx.x * blockDim.x + threadIdx.x;
    if (t >= PB * PB * 3) return;
    int c = t % 3;
    int j = (t / 3) % PB;
    int i = t / (3 * PB);

    const float w0[4] = {0.25f, 0.75f, 0.75f, 0.25f};
    int by = 2 * i - 1, bx = 2 * j - 1;
    float wy[4], wx[4], sy = 0.f, sx = 0.f;
#pragma unroll
    for (int u = 0; u < 4; u++) { int r = by + u; wy[u] = (r >= 0 && r < PHW) ? w0[u] : 0.f; sy += wy[u]; }
#pragma unroll
    for (int v = 0; v < 4; v++) { int q = bx + v; wx[v] = (q >= 0 && q < PHW) ? w0[v] : 0.f; sx += wx[v]; }

    float acc = 0.f;
#pragma unroll
    for (int u = 0; u < 4; u++) {
        if (wy[u] == 0.f) continue;
        int r = by + u;
        float rowacc = 0.f;
#pragma unroll
        for (int v = 0; v < 4; v++) {
            if (wx[v] == 0.f) continue;
            rowacc += wx[v] * __ldg(&patch[(r * PHW + (bx + v)) * 3 + c]);
        }
        acc += wy[u] * rowacc;
    }
    g_small[t] = acc / (sy * sx);
}

// ---------------------------------------------------------------------------
// K2: paste transformed tiles over the copied images.
// Forward transform order: rot90(k=1) if d0, flip_lr if d1, flip_ud if d2.
// tile[y,x] = small[sy,sx] with the composed inverse index map.
// Sequential-scan semantics: a pixel belongs to the LAST covering box of its
// batch, so each (box,pixel) thread skips itself if a later box covers it.
// ---------------------------------------------------------------------------
__global__ void k_paste(const int* __restrict__ box_yx, const int* __restrict__ dec,
                        float* __restrict__ out) {
    int box = blockIdx.x;       // 0..127
    int row = blockIdx.y;       // 0..127
    int b = box >> 4;
    int n = box & 15;
    int y0 = __ldg(&box_yx[box * 2 + 0]);
    int x0 = __ldg(&box_yx[box * 2 + 1]);
    int yg = y0 + row;

    int tid = threadIdx.x;      // 0..383 (one image row slice: 128 px * 3 ch)
    int x = tid / 3;
    int c = tid - 3 * x;
    int xg = x0 + x;

    // later box in same batch covering this pixel wins -> skip
    for (int m = n + 1; m < NPER; ++m) {
        int idx = (b * NPER + m) * 2;
        int yb = __ldg(&box_yx[idx]);
        int xb = __ldg(&box_yx[idx + 1]);
        if ((unsigned)(yg - yb) < PB && (unsigned)(xg - xb) < PB) return;
    }

    int d0 = __ldg(&dec[box * 3 + 0]);
    int d1 = __ldg(&dec[box * 3 + 1]);
    int d2 = __ldg(&dec[box * 3 + 2]);

    int y2 = d2 ? (PB - 1 - row) : row;
    int x1 = d1 ? (PB - 1 - x)   : x;
    int sy = d0 ? x1            : y2;
    int sx = d0 ? (PB - 1 - y2) : x1;

    out[((b * HW + yg) * HW + xg) * 3 + c] = g_small[(sy * PB + sx) * 3 + c];
}

// ---------------------------------------------------------------------------
// K3: gradient gather + inverse transform + sum over all 128 boxes.
// Inverse order: flip_ud if d2, flip_lr if d1, rot90(k=3) if d0.
// Since upsampling is linear, sum BEFORE upsampling (one thread per acc elem,
// full sum in a register — no atomics, no zero-init needed).
// ---------------------------------------------------------------------------
__global__ void k_gather(const float* __restrict__ grads,
                         const int* __restrict__ box_yx,
                         const int* __restrict__ dec) {
    __shared__ int sy_[NB], sx_[NB], sd_[NB];
    int tid = threadIdx.x;      // 0..383
    if (tid < NB) {
        sy_[tid] = box_yx[tid * 2];
        sx_[tid] = box_yx[tid * 2 + 1];
        sd_[tid] = (dec[tid * 3] > 0 ? 1 : 0) |
                   (dec[tid * 3 + 1] > 0 ? 2 : 0) |
                   (dec[tid * 3 + 2] > 0 ? 4 : 0);
    }
    __syncthreads();

    int i = blockIdx.x;         // row of 128x128 accumulator
    int j = tid / 3;
    int c = tid - 3 * j;

    float s = 0.f;
#pragma unroll 4
    for (int box = 0; box < NB; ++box) {
        int d = sd_[box];
        int p, q;
        if (d & 1) { p = PB - 1 - j; q = i; }     // rot90 k=3: h[i,j] = m[127-j, i]
        else       { p = i;          q = j; }
        int r   = (d & 4) ? (PB - 1 - p) : p;     // undo flip_ud
        int col = (d & 2) ? (PB - 1 - q) : q;     // undo flip_lr
        int b = box >> 4;
        s += __ldg(&grads[((b * HW + sy_[box] + r) * HW + (sx_[box] + col)) * 3 + c]);
    }
    g_acc[i * (PB * 3) + tid] = s;
}

// ---------------------------------------------------------------------------
// K4: bilinear upsample g_acc 128->256 (half-pixel, clamped == JAX renorm for
// 2-tap case) + analytic TV-loss gradient of the patch. Writes agg output.
// ---------------------------------------------------------------------------
__global__ void k_final(const float* __restrict__ patch, float* __restrict__ agg) {
    int t = blockIdx.x * blockDim.x + threadIdx.x;
    if (t >= PHW * PHW * 3) return;
    int c = t % 3;
    int j = (t / 3) % PHW;
    int i = t / (PHW * 3);

    // upsample weights: even idx -> (k-1:0.25, k:0.75); odd -> (k:0.75, k+1:0.25)
    int ky = i >> 1, y0, y1; float wy0, wy1;
    if (i & 1) { y0 = ky;                 y1 = min(ky + 1, PB - 1); wy0 = 0.75f; wy1 = 0.25f; }
    else       { y0 = max(ky - 1, 0);     y1 = ky;                  wy0 = 0.25f; wy1 = 0.75f; }
    int kx = j >> 1, x0, x1; float wx0, wx1;
    if (j & 1) { x0 = kx;                 x1 = min(kx + 1, PB - 1); wx0 = 0.75f; wx1 = 0.25f; }
    else       { x0 = max(kx - 1, 0);     x1 = kx;                  wx0 = 0.25f; wx1 = 0.75f; }

    float v = wy0 * (wx0 * g_acc[(y0 * PB + x0) * 3 + c] + wx1 * g_acc[(y0 * PB + x1) * 3 + c])
            + wy1 * (wx0 * g_acc[(y1 * PB + x0) * 3 + c] + wx1 * g_acc[(y1 * PB + x1) * 3 + c]);

    // TV-loss gradient: L = 0.5 * sum sqrt(a^2 + b^2 + eps),
    // a(i,j) = p[i,j]-p[i,j+1] (0 at last col), b(i,j) = p[i,j]-p[i+1,j] (0 at last row)
    float pij = __ldg(&patch[(i * PHW + j) * 3 + c]);
    float a = (j < PHW - 1) ? (pij - __ldg(&patch[(i * PHW + j + 1) * 3 + c])) : 0.f;
    float b = (i < PHW - 1) ? (pij - __ldg(&patch[((i + 1) * PHW + j) * 3 + c])) : 0.f;
    float g = (a + b) * rsqrtf(a * a + b * b + 1e-12f);
    if (j > 0) {
        float pl = __ldg(&patch[(i * PHW + j - 1) * 3 + c]);
        float al = pl - pij;
        float bl = (i < PHW - 1) ? (pl - __ldg(&patch[((i + 1) * PHW + j - 1) * 3 + c])) : 0.f;
        g -= al * rsqrtf(al * al + bl * bl + 1e-12f);
    }
    if (i > 0) {
        float pu = __ldg(&patch[((i - 1) * PHW + j) * 3 + c]);
        float bu = pu - pij;
        float au = (j < PHW - 1) ? (pu - __ldg(&patch[((i - 1) * PHW + j + 1) * 3 + c])) : 0.f;
        g -= bu * rsqrtf(au * au + bu * bu + 1e-12f);
    }
    agg[t] = v + 0.5f * g;
}

// ---------------------------------------------------------------------------
extern "C" void kernel_launch(void* const* d_in, const int* in_sizes, int n_in,
                              void* d_out, int out_size) {
    const float* images = (const float*)d_in[0];
    const float* grads  = (const float*)d_in[1];
    const float* patch  = (const float*)d_in[2];
    const int*   box_yx = (const int*)d_in[3];
    const int*   dec    = (const int*)d_in[4];

    float* out = (float*)d_out;
    size_t img_elems = (size_t)BIMG * HW * HW * 3;
    float* agg = out + img_elems;

    // K1: patch -> g_small (tiny)
    k_downsample<<<(PB * PB * 3 + 255) / 256, 256>>>(patch);

    // bulk copy images -> output (dominant HBM traffic)
    cudaMemcpyAsync(out, images, img_elems * sizeof(float), cudaMemcpyDeviceToDevice);

    // K2: overwrite pasted boxes (later-box-wins semantics)
    dim3 pg(NB, PB);
    k_paste<<<pg, PB * 3>>>(box_yx, dec, out);

    // K3: gradient gather + inverse transforms + register-sum over 128 boxes
    k_gather<<<PB, PB * 3>>>(grads, box_yx, dec);

    // K4: upsample + TV grad -> agg output
    k_final<<<(PHW * PHW * 3 + 255) / 256, 256>>>(patch, agg);
}

// round 2
// speedup vs baseline: 1.7043x; 1.7043x over previous
#include <cuda_runtime.h>

#define PB   128          // pasted box size
#define PHW  256          // patch resolution
#define HW   1024         // image H = W
#define BIMG 8            // batch
#define NPER 16           // boxes per image
#define NB   128          // total boxes
#define NGRP 4            // gather box-groups (parallelism)
#define BOXES_PER_GRP (NB / NGRP / BIMG)   // not used directly; groups span all batches

// Scratch (device globals — no allocation allowed)
__device__ float g_small[PB * PB * 3];                 // downsampled patch
__device__ float g_accp[NGRP * PB * PB * 3];           // partial gather sums

// ---------------------------------------------------------------------------
// K1: antialiased bilinear downsample patch 256->128 (JAX triangle taps
// {0.25,0.75,0.75,0.25} with per-dim edge renormalization)
// ---------------------------------------------------------------------------
__global__ void k_downsample(const float* __restrict__ patch) {
    int t = blockIdx.x * blockDim.x + threadIdx.x;
    if (t >= PB * PB * 3) return;
    int c = t % 3;
    int j = (t / 3) % PB;
    int i = t / (3 * PB);

    const float w0[4] = {0.25f, 0.75f, 0.75f, 0.25f};
    int by = 2 * i - 1, bx = 2 * j - 1;
    float wy[4], wx[4], sy = 0.f, sx = 0.f;
#pragma unroll
    for (int u = 0; u < 4; u++) { int r = by + u; wy[u] = (r >= 0 && r < PHW) ? w0[u] : 0.f; sy += wy[u]; }
#pragma unroll
    for (int v = 0; v < 4; v++) { int q = bx + v; wx[v] = (q >= 0 && q < PHW) ? w0[v] : 0.f; sx += wx[v]; }

    float acc = 0.f;
#pragma unroll
    for (int u = 0; u < 4; u++) {
        if (wy[u] == 0.f) continue;
        int r = by + u;
        float rowacc = 0.f;
#pragma unroll
        for (int v = 0; v < 4; v++) {
            if (wx[v] == 0.f) continue;
            rowacc += wx[v] * __ldg(&patch[(r * PHW + (bx + v)) * 3 + c]);
        }
        acc += wy[u] * rowacc;
    }
    g_small[t] = acc / (sy * sx);
}

// ---------------------------------------------------------------------------
// K2: fused copy + paste. One block per image row. Fast-path float4 copy;
// pixels under a box resolve the LAST covering box (scan-paste semantics).
// ---------------------------------------------------------------------------
__global__ void __launch_bounds__(256) k_copy_paste(
        const float* __restrict__ images,
        const int* __restrict__ box_yx, const int* __restrict__ dec,
        float* __restrict__ out) {
    int b = blockIdx.x >> 10;            // image
    int y = blockIdx.x & 1023;           // row
    int tid = threadIdx.x;

    __shared__ unsigned s_mask;
    __shared__ int s_x0[NPER];
    __shared__ int s_ry[NPER];
    __shared__ int s_d[NPER];

    if (tid < 32) {
        int covered = 0;
        if (tid < NPER) {
            int box = b * NPER + tid;
            int y0 = __ldg(&box_yx[box * 2]);
            int x0 = __ldg(&box_yx[box * 2 + 1]);
            s_x0[tid] = x0;
            s_ry[tid] = y - y0;
            s_d[tid] = (__ldg(&dec[box * 3]) > 0 ? 1 : 0) |
                       (__ldg(&dec[box * 3 + 1]) > 0 ? 2 : 0) |
                       (__ldg(&dec[box * 3 + 2]) > 0 ? 4 : 0);
            covered = ((unsigned)(y - y0) < (unsigned)PB);
        }
        unsigned m = __ballot_sync(0xFFFFFFFFu, covered) & 0xFFFFu;
        if (tid == 0) s_mask = m;
    }
    __syncthreads();

    size_t rowbase = ((size_t)(b * HW + y)) * (HW * 3);   // float offset of row
    const float4* src4 = (const float4*)(images + rowbase);
    float4* dst4 = (float4*)(out + rowbase);
    unsigned mask = s_mask;

    if (mask == 0) {
        // pure copy row: 768 float4
#pragma unroll
        for (int k = 0; k < 3; k++) {
            int q = tid + k * 256;
            __stcs(&dst4[q], __ldcs(&src4[q]));
        }
        return;
    }

#pragma unroll
    for (int k = 0; k < 3; k++) {
        int q = tid + k * 256;           // float4 index in row
        int fo = q * 4;                  // float offset in row
        int pa = fo / 3;                 // first pixel spanned
        // find covering boxes (highest n wins) for pixels pa and pa+1
        int boxa = -1, boxb = -1;
        unsigned m = mask;
        while (m) {
            int n = 31 - __clz(m);
            m &= ~(1u << n);
            int x0 = s_x0[n];
            if (boxa < 0 && (unsigned)(pa - x0) < (unsigned)PB) boxa = n;
            if (boxb < 0 && (unsigned)(pa + 1 - x0) < (unsigned)PB) boxb = n;
            if (boxa >= 0 && boxb >= 0) break;
        }
        if (boxa < 0 && boxb < 0) {
            __stcs(&dst4[q], __ldcs(&src4[q]));
            continue;
        }
        float4 v = __ldcs(&src4[q]);
        float* vf = (float*)&v;
#pragma unroll
        for (int e = 0; e < 4; e++) {
            int fe = fo + e;
            int px = fe / 3;
            int box = (px == pa) ? boxa : boxb;
            if (box < 0) continue;
            int c = fe - 3 * px;
            int rx = px - s_x0[box];
            int ry = s_ry[box];
            int d = s_d[box];
            int y2 = (d & 4) ? (PB - 1 - ry) : ry;
            int x1 = (d & 2) ? (PB - 1 - rx) : rx;
            int sy_ = (d & 1) ? x1 : y2;
            int sx_ = (d & 1) ? (PB - 1 - y2) : x1;
            vf[e] = g_small[(sy_ * PB + sx_) * 3 + c];
        }
        __stcs(&dst4[q], v);
    }
}

// ---------------------------------------------------------------------------
// K3: gradient gather + inverse transform, partial sums over NGRP box groups.
// blockIdx.x = accumulator row i, blockIdx.y = group g (32 boxes each).
// ---------------------------------------------------------------------------
__global__ void __launch_bounds__(384) k_gather(
        const float* __restrict__ grads,
        const int* __restrict__ box_yx,
        const int* __restrict__ dec) {
    const int NBG = NB / NGRP;           // 32 boxes per group
    __shared__ int sy_[NBG], sx_[NBG], sd_[NBG], sb_[NBG];
    int tid = threadIdx.x;               // 0..383
    int g = blockIdx.y;
    if (tid < NBG) {
        int box = g * NBG + tid;
        sy_[tid] = box_yx[box * 2];
        sx_[tid] = box_yx[box * 2 + 1];
        sd_[tid] = (dec[box * 3] > 0 ? 1 : 0) |
                   (dec[box * 3 + 1] > 0 ? 2 : 0) |
                   (dec[box * 3 + 2] > 0 ? 4 : 0);
        sb_[tid] = box >> 4;             // batch index
    }
    __syncthreads();

    int i = blockIdx.x;                  // row of accumulator
    int j = tid / 3;
    int c = tid - 3 * j;

    float s = 0.f;
#pragma unroll 8
    for (int k = 0; k < NBG; ++k) {
        int d = sd_[k];
        int p, q;
        if (d & 1) { p = PB - 1 - j; q = i; }      // undo rot90(k=1) via rot90(k=3)
        else       { p = i;          q = j; }
        int r   = (d & 4) ? (PB - 1 - p) : p;      // undo flip_ud
        int col = (d & 2) ? (PB - 1 - q) : q;      // undo flip_lr
        s += __ldg(&grads[(((size_t)sb_[k] * HW + sy_[k] + r) * HW + (sx_[k] + col)) * 3 + c]);
    }
    g_accp[(g * PB + i) * (PB * 3) + tid] = s;
}

// ---------------------------------------------------------------------------
// K4: reduce partials + bilinear upsample 128->256 + analytic TV gradient.
// ---------------------------------------------------------------------------
__device__ __forceinline__ float acc_at(int y, int x, int c) {
    float s = 0.f;
#pragma unroll
    for (int g = 0; g < NGRP; g++)
        s += g_accp[(g * PB + y) * (PB * 3) + x * 3 + c];
    return s;
}

__global__ void k_final(const float* __restrict__ patch, float* __restrict__ agg) {
    int t = blockIdx.x * blockDim.x + threadIdx.x;
    if (t >= PHW * PHW * 3) return;
    int c = t % 3;
    int j = (t / 3) % PHW;
    int i = t / (PHW * 3);

    int ky = i >> 1, y0, y1; float wy0, wy1;
    if (i & 1) { y0 = ky;             y1 = min(ky + 1, PB - 1); wy0 = 0.75f; wy1 = 0.25f; }
    else       { y0 = max(ky - 1, 0); y1 = ky;                  wy0 = 0.25f; wy1 = 0.75f; }
    int kx = j >> 1, x0, x1; float wx0, wx1;
    if (j & 1) { x0 = kx;             x1 = min(kx + 1, PB - 1); wx0 = 0.75f; wx1 = 0.25f; }
    else       { x0 = max(kx - 1, 0); x1 = kx;                  wx0 = 0.25f; wx1 = 0.75f; }

    float v = wy0 * (wx0 * acc_at(y0, x0, c) + wx1 * acc_at(y0, x1, c))
            + wy1 * (wx0 * acc_at(y1, x0, c) + wx1 * acc_at(y1, x1, c));

    // analytic TV grad: L = 0.5 * sum sqrt(a^2+b^2+eps)
    float pij = __ldg(&patch[(i * PHW + j) * 3 + c]);
    float a = (j < PHW - 1) ? (pij - __ldg(&patch[(i * PHW + j + 1) * 3 + c])) : 0.f;
    float b = (i < PHW - 1) ? (pij - __ldg(&patch[((i + 1) * PHW + j) * 3 + c])) : 0.f;
    float g = (a + b) * rsqrtf(a * a + b * b + 1e-12f);
    if (j > 0) {
        float pl = __ldg(&patch[(i * PHW + j - 1) * 3 + c]);
        float al = pl - pij;
        float bl = (i < PHW - 1) ? (pl - __ldg(&patch[((i + 1) * PHW + j - 1) * 3 + c])) : 0.f;
        g -= al * rsqrtf(al * al + bl * bl + 1e-12f);
    }
    if (i > 0) {
        float pu = __ldg(&patch[((i - 1) * PHW + j) * 3 + c]);
        float bu = pu - pij;
        float au = (j < PHW - 1) ? (pu - __ldg(&patch[((i - 1) * PHW + j + 1) * 3 + c])) : 0.f;
        g -= bu * rsqrtf(au * au + bu * bu + 1e-12f);
    }
    agg[t] = v + 0.5f * g;
}

// ---------------------------------------------------------------------------
extern "C" void kernel_launch(void* const* d_in, const int* in_sizes, int n_in,
                              void* d_out, int out_size) {
    const float* images = (const float*)d_in[0];
    const float* grads  = (const float*)d_in[1];
    const float* patch  = (const float*)d_in[2];
    const int*   box_yx = (const int*)d_in[3];
    const int*   dec    = (const int*)d_in[4];

    float* out = (float*)d_out;
    size_t img_elems = (size_t)BIMG * HW * HW * 3;
    float* agg = out + img_elems;

    // K1: patch -> g_small (tiny, must precede K2)
    k_downsample<<<(PB * PB * 3 + 255) / 256, 256>>>(patch);

    // K3: gather partials (independent of K1/K2; interleave to hide K1 latency)
    dim3 gg(PB, NGRP);
    k_gather<<<gg, PB * 3>>>(grads, box_yx, dec);

    // K2: fused copy + paste (dominant HBM traffic, single pass)
    k_copy_paste<<<BIMG * HW, 256>>>(images, box_yx, dec, out);

    // K4: reduce + upsample + TV grad
    k_final<<<(PHW * PHW * 3 + 255) / 256, 256>>>(patch, agg);
}

// round 3
// speedup vs baseline: 1.8032x; 1.0580x over previous
#include <cuda_runtime.h>

#define PB   128
#define PHW  256
#define HW   1024
#define BIMG 8
#define NPER 16
#define NB   128
#define NGRP 4
#define NBG  (NB / NGRP)          // 32 boxes per gather group

#define THREADS    384
#define DS_BLOCKS  128            // 128*384 = 49152 = PB*PB*3
#define GT_BLOCKS  (NGRP * PB)    // 512
#define CP_BLOCKS  (BIMG * HW)    // 8192
#define FN_BLOCKS  512            // 512*384 = 196608 = PHW*PHW*3
#define TOTAL_BLOCKS (DS_BLOCKS + GT_BLOCKS + CP_BLOCKS + FN_BLOCKS)

// Scratch (device globals — no allocation allowed)
__device__ float g_small[PB * PB * 3];              // downsampled patch
__device__ float g_nr[NGRP][PB][PB * 3];            // non-rot gather partials (row-major)
__device__ float g_rt[NGRP][PB][PB * 3];            // rot gather partials (TRANSPOSED: [x][y*3+c])
__device__ int   g_sync[2];                          // [0]=downsample done blocks, [1]=gather done blocks

// ---------------------------------------------------------------------------
// Role: antialiased bilinear downsample 256->128 (JAX triangle taps
// {0.25,0.75,0.75,0.25}, per-dim edge renormalization).
// ---------------------------------------------------------------------------
__device__ void role_downsample(int bid, const float* __restrict__ patch) {
    int t = bid * THREADS + threadIdx.x;             // 0..49151 exactly
    int c = t % 3;
    int j = (t / 3) % PB;
    int i = t / (3 * PB);

    const float w0[4] = {0.25f, 0.75f, 0.75f, 0.25f};
    int by = 2 * i - 1, bx = 2 * j - 1;
    float wy[4], wx[4], sy = 0.f, sx = 0.f;
#pragma unroll
    for (int u = 0; u < 4; u++) { int r = by + u; wy[u] = (r >= 0 && r < PHW) ? w0[u] : 0.f; sy += wy[u]; }
#pragma unroll
    for (int v = 0; v < 4; v++) { int q = bx + v; wx[v] = (q >= 0 && q < PHW) ? w0[v] : 0.f; sx += wx[v]; }

    float acc = 0.f;
#pragma unroll
    for (int u = 0; u < 4; u++) {
        if (wy[u] == 0.f) continue;
        int r = by + u;
        float rowacc = 0.f;
#pragma unroll
        for (int v = 0; v < 4; v++) {
            if (wx[v] == 0.f) continue;
            rowacc += wx[v] * __ldg(&patch[(r * PHW + (bx + v)) * 3 + c]);
        }
        acc += wy[u] * rowacc;
    }
    g_small[t] = acc / (sy * sx);

    __syncthreads();
    __threadfence();
    if (threadIdx.x == 0) atomicAdd(&g_sync[0], 1);
}

// ---------------------------------------------------------------------------
// Role: gradient gather + inverse transform. Block = (group g, index r).
// Non-rot boxes -> output row r (coalesced reads).
// Rot boxes     -> output column r: acc[i][r] reads a FIXED source row, i
// varying with thread -> also coalesced. Stored transposed in g_rt.
// ---------------------------------------------------------------------------
__device__ void role_gather(int gb, const float* __restrict__ grads,
                            const int* __restrict__ box_yx,
                            const int* __restrict__ dec) {
    __shared__ int s_y[NBG], s_x[NBG], s_d[NBG], s_b[NBG];
    int tid = threadIdx.x;
    int g = gb >> 7;           // 0..NGRP-1
    int r = gb & 127;          // 0..127

    if (tid < NBG) {
        int box = g * NBG + tid;
        s_y[tid] = __ldg(&box_yx[box * 2]);
        s_x[tid] = __ldg(&box_yx[box * 2 + 1]);
        s_d[tid] = (__ldg(&dec[box * 3]) > 0 ? 1 : 0) |
                   (__ldg(&dec[box * 3 + 1]) > 0 ? 2 : 0) |
                   (__ldg(&dec[box * 3 + 2]) > 0 ? 4 : 0);
        s_b[tid] = box >> 4;
    }
    __syncthreads();

    int j = tid / 3;           // pixel index along the varying axis
    int c = tid - 3 * j;

    float acc_nr = 0.f;        // out(i=r, j)
    float acc_rt = 0.f;        // out(i=j, j=r)  (thread's j plays the i role)
#pragma unroll 4
    for (int k = 0; k < NBG; ++k) {
        int d = s_d[k];
        size_t base = (size_t)s_b[k] * (HW * HW * 3);
        if (d & 1) {
            // rot box: acc[i][r] += g[b, sy + ((d&4)? r : 127-r), sx + ((d&2)? 127-i : i)]
            int row = s_y[k] + ((d & 4) ? r : (PB - 1 - r));
            int col = s_x[k] + ((d & 2) ? (PB - 1 - j) : j);
            acc_rt += __ldg(&grads[base + ((size_t)row * HW + col) * 3 + c]);
        } else {
            // non-rot: acc[r][j] += g[b, sy + ((d&4)? 127-r : r), sx + ((d&2)? 127-j : j)]
            int row = s_y[k] + ((d & 4) ? (PB - 1 - r) : r);
            int col = s_x[k] + ((d & 2) ? (PB - 1 - j) : j);
            acc_nr += __ldg(&grads[base + ((size_t)row * HW + col) * 3 + c]);
        }
    }
    g_nr[g][r][tid] = acc_nr;
    g_rt[g][r][tid] = acc_rt;   // transposed storage: [column r][i*3+c]

    __syncthreads();
    __threadfence();
    if (tid == 0) atomicAdd(&g_sync[1], 1);
}

// ---------------------------------------------------------------------------
// Role: fused copy + paste, one block per image row. Streaming float4 copy;
// fully-pasted quads skip the source read entirely.
// ---------------------------------------------------------------------------
__device__ void role_copy(int cb, const float* __restrict__ images,
                          const int* __restrict__ box_yx, const int* __restrict__ dec,
                          float* __restrict__ out) {
    int b = cb >> 10;
    int y = cb & 1023;
    int tid = threadIdx.x;

    __shared__ unsigned s_mask;
    __shared__ int s_x0[NPER];
    __shared__ int s_ry[NPER];
    __shared__ int s_d[NPER];

    if (tid < 32) {
        int covered = 0;
        if (tid < NPER) {
            int box = b * NPER + tid;
            int y0 = __ldg(&box_yx[box * 2]);
            s_x0[tid] = __ldg(&box_yx[box * 2 + 1]);
            s_ry[tid] = y - y0;
            s_d[tid] = (__ldg(&dec[box * 3]) > 0 ? 1 : 0) |
                       (__ldg(&dec[box * 3 + 1]) > 0 ? 2 : 0) |
                       (__ldg(&dec[box * 3 + 2]) > 0 ? 4 : 0);
            covered = ((unsigned)(y - y0) < (unsigned)PB);
        }
        unsigned m = __ballot_sync(0xFFFFFFFFu, covered) & 0xFFFFu;
        if (tid == 0) s_mask = m;
    }
    __syncthreads();

    size_t rowbase = ((size_t)(b * HW + y)) * (HW * 3);
    const float4* src4 = (const float4*)(images + rowbase);
    float4* dst4 = (float4*)(out + rowbase);
    unsigned mask = s_mask;

    if (mask == 0) {
#pragma unroll
        for (int k = 0; k < 2; k++) {
            int q = tid + k * THREADS;
            __stcs(&dst4[q], __ldcs(&src4[q]));
        }
        return;
    }

    // covered row: wait for downsample completion
    if (tid == 0) {
        volatile int* p = &g_sync[0];
        while (*p < DS_BLOCKS) __nanosleep(64);
    }
    __syncthreads();

#pragma unroll
    for (int k = 0; k < 2; k++) {
        int q = tid + k * THREADS;
        int fo = q * 4;
        int pa = fo / 3;
        int boxa = -1, boxb = -1;
        unsigned m = mask;
        while (m) {
            int n = 31 - __clz(m);
            m &= ~(1u << n);
            int x0 = s_x0[n];
            if (boxa < 0 && (unsigned)(pa - x0) < (unsigned)PB) boxa = n;
            if (boxb < 0 && (unsigned)(pa + 1 - x0) < (unsigned)PB) boxb = n;
            if ((boxa | boxb) >= 0 && boxa >= 0 && boxb >= 0) break;
        }
        if (boxa < 0 && boxb < 0) {
            __stcs(&dst4[q], __ldcs(&src4[q]));
            continue;
        }
        float4 v;
        if (boxa < 0 || boxb < 0) v = __ldcs(&src4[q]);   // partial coverage needs source
        float* vf = (float*)&v;
#pragma unroll
        for (int e = 0; e < 4; e++) {
            int fe = fo + e;
            int px = fe / 3;
            int box = (px == pa) ? boxa : boxb;
            if (box < 0) continue;
            int c = fe - 3 * px;
            int rx = px - s_x0[box];
            int ry = s_ry[box];
            int d = s_d[box];
            int y2 = (d & 4) ? (PB - 1 - ry) : ry;
            int x1 = (d & 2) ? (PB - 1 - rx) : rx;
            int sy_ = (d & 1) ? x1 : y2;
            int sx_ = (d & 1) ? (PB - 1 - y2) : x1;
            vf[e] = g_small[(sy_ * PB + sx_) * 3 + c];
        }
        __stcs(&dst4[q], v);
    }
}

// ---------------------------------------------------------------------------
// Role: reduce gather partials + bilinear upsample 128->256 + analytic TV grad.
// ---------------------------------------------------------------------------
__device__ __forceinline__ float acc_at(int y, int x, int c) {
    float s = 0.f;
#pragma unroll
    for (int g = 0; g < NGRP; g++) {
        s += g_nr[g][y][x * 3 + c];
        s += g_rt[g][x][y * 3 + c];   // transposed partials
    }
    return s;
}

__device__ void role_final(int fb, const float* __restrict__ patch,
                           float* __restrict__ agg) {
    if (threadIdx.x == 0) {
        volatile int* p = &g_sync[1];
        while (*p < GT_BLOCKS) __nanosleep(64);
    }
    __syncthreads();

    int t = fb * THREADS + threadIdx.x;   // 0..196607 exactly
    int c = t % 3;
    int j = (t / 3) % PHW;
    int i = t / (PHW * 3);

    int ky = i >> 1, y0, y1; float wy0, wy1;
    if (i & 1) { y0 = ky;             y1 = min(ky + 1, PB - 1); wy0 = 0.75f; wy1 = 0.25f; }
    else       { y0 = max(ky - 1, 0); y1 = ky;                  wy0 = 0.25f; wy1 = 0.75f; }
    int kx = j >> 1, x0, x1; float wx0, wx1;
    if (j & 1) { x0 = kx;             x1 = min(kx + 1, PB - 1); wx0 = 0.75f; wx1 = 0.25f; }
    else       { x0 = max(kx - 1, 0); x1 = kx;                  wx0 = 0.25f; wx1 = 0.75f; }

    float v = wy0 * (wx0 * acc_at(y0, x0, c) + wx1 * acc_at(y0, x1, c))
            + wy1 * (wx0 * acc_at(y1, x0, c) + wx1 * acc_at(y1, x1, c));

    // analytic TV grad: L = 0.5 * sum sqrt(a^2+b^2+eps)
    float pij = __ldg(&patch[(i * PHW + j) * 3 + c]);
    float a = (j < PHW - 1) ? (pij - __ldg(&patch[(i * PHW + j + 1) * 3 + c])) : 0.f;
    float b = (i < PHW - 1) ? (pij - __ldg(&patch[((i + 1) * PHW + j) * 3 + c])) : 0.f;
    float g = (a + b) * rsqrtf(a * a + b * b + 1e-12f);
    if (j > 0) {
        float pl = __ldg(&patch[(i * PHW + j - 1) * 3 + c]);
        float al = pl - pij;
        float bl = (i < PHW - 1) ? (pl - __ldg(&patch[((i + 1) * PHW + j - 1) * 3 + c])) : 0.f;
        g -= al * rsqrtf(al * al + bl * bl + 1e-12f);
    }
    if (i > 0) {
        float pu = __ldg(&patch[((i - 1) * PHW + j) * 3 + c]);
        float bu = pu - pij;
        float au = (j < PHW - 1) ? (pu - __ldg(&patch[((i - 1) * PHW + j + 1) * 3 + c])) : 0.f;
        g -= bu * rsqrtf(au * au + bu * bu + 1e-12f);
    }
    agg[t] = v + 0.5f * g;
}

// ---------------------------------------------------------------------------
// Mega kernel: one launch, block roles by blockIdx.x. Producers occupy the
// lowest block ids (guaranteed wave-1 residency); spinners are bounded well
// below the resident-CTA capacity, so forward progress is guaranteed.
// ---------------------------------------------------------------------------
__global__ void __launch_bounds__(THREADS) k_mega(
        const float* __restrict__ images, const float* __restrict__ grads,
        const float* __restrict__ patch,
        const int* __restrict__ box_yx, const int* __restrict__ dec,
        float* __restrict__ out, float* __restrict__ agg) {
    int bid = blockIdx.x;
    if (bid < DS_BLOCKS) {
        role_downsample(bid, patch);
    } else if (bid < DS_BLOCKS + GT_BLOCKS) {
        role_gather(bid - DS_BLOCKS, grads, box_yx, dec);
    } else if (bid < DS_BLOCKS + GT_BLOCKS + CP_BLOCKS) {
        role_copy(bid - (DS_BLOCKS + GT_BLOCKS), images, box_yx, dec, out);
    } else {
        role_final(bid - (DS_BLOCKS + GT_BLOCKS + CP_BLOCKS), patch, agg);
    }
}

// ---------------------------------------------------------------------------
extern "C" void kernel_launch(void* const* d_in, const int* in_sizes, int n_in,
                              void* d_out, int out_size) {
    const float* images = (const float*)d_in[0];
    const float* grads  = (const float*)d_in[1];
    const float* patch  = (const float*)d_in[2];
    const int*   box_yx = (const int*)d_in[3];
    const int*   dec    = (const int*)d_in[4];

    float* out = (float*)d_out;
    size_t img_elems = (size_t)BIMG * HW * HW * 3;
    float* agg = out + img_elems;

    // reset sync counters (graph-capturable memset node; deterministic per replay)
    void* sptr = nullptr;
    cudaGetSymbolAddress(&sptr, g_sync);
    cudaMemsetAsync(sptr, 0, 2 * sizeof(int));

    k_mega<<<TOTAL_BLOCKS, THREADS>>>(images, grads, patch, box_yx, dec, out, agg);
}

// round 4
// speedup vs baseline: 1.8431x; 1.0222x over previous
#include <cuda_runtime.h>

#define PB   128
#define PHW  256
#define HW   1024
#define BIMG 8
#define NPER 16
#define NB   128
#define NGRP 4
#define NBG  (NB / NGRP)          // 32 boxes per gather group

#define THREADS    384
#define DS_BLOCKS  128            // 128*384 = 49152 = PB*PB*3
#define GT_BLOCKS  (NGRP * PB)    // 512
#define ROWS_PER_CP 4
#define CP_BLOCKS  (BIMG * HW / ROWS_PER_CP)   // 2048
#define FN_BLOCKS  512            // 512*384 = 196608 = PHW*PHW*3
#define TOTAL_BLOCKS (DS_BLOCKS + GT_BLOCKS + CP_BLOCKS + FN_BLOCKS)

// Scratch (device globals — no allocation allowed)
__device__ float g_small[PB * PB * 3];              // downsampled patch
__device__ float g_nr[NGRP][PB][PB * 3];            // non-rot gather partials
__device__ float g_rt[NGRP][PB][PB * 3];            // rot gather partials (transposed)
__device__ int   g_sync[2];                          // [0]=ds done, [1]=gather done

// ---------------------------------------------------------------------------
// Role: antialiased bilinear downsample 256->128 (JAX triangle taps
// {0.25,0.75,0.75,0.25}, per-dim edge renormalization).
// ---------------------------------------------------------------------------
__device__ void role_downsample(int bid, const float* __restrict__ patch) {
    int t = bid * THREADS + threadIdx.x;
    int c = t % 3;
    int j = (t / 3) % PB;
    int i = t / (3 * PB);

    const float w0[4] = {0.25f, 0.75f, 0.75f, 0.25f};
    int by = 2 * i - 1, bx = 2 * j - 1;
    float wy[4], wx[4], sy = 0.f, sx = 0.f;
#pragma unroll
    for (int u = 0; u < 4; u++) { int r = by + u; wy[u] = (r >= 0 && r < PHW) ? w0[u] : 0.f; sy += wy[u]; }
#pragma unroll
    for (int v = 0; v < 4; v++) { int q = bx + v; wx[v] = (q >= 0 && q < PHW) ? w0[v] : 0.f; sx += wx[v]; }

    float acc = 0.f;
#pragma unroll
    for (int u = 0; u < 4; u++) {
        if (wy[u] == 0.f) continue;
        int r = by + u;
        float rowacc = 0.f;
#pragma unroll
        for (int v = 0; v < 4; v++) {
            if (wx[v] == 0.f) continue;
            rowacc += wx[v] * __ldg(&patch[(r * PHW + (bx + v)) * 3 + c]);
        }
        acc += wy[u] * rowacc;
    }
    g_small[t] = acc / (sy * sx);

    __syncthreads();
    __threadfence();
    if (threadIdx.x == 0) atomicAdd(&g_sync[0], 1);
}

// ---------------------------------------------------------------------------
// Role: gradient gather + inverse transform (coalesced for rot and non-rot).
// ---------------------------------------------------------------------------
__device__ void role_gather(int gb, const float* __restrict__ grads,
                            const int* __restrict__ box_yx,
                            const int* __restrict__ dec) {
    __shared__ int s_y[NBG], s_x[NBG], s_d[NBG], s_b[NBG];
    int tid = threadIdx.x;
    int g = gb >> 7;
    int r = gb & 127;

    if (tid < NBG) {
        int box = g * NBG + tid;
        s_y[tid] = __ldg(&box_yx[box * 2]);
        s_x[tid] = __ldg(&box_yx[box * 2 + 1]);
        s_d[tid] = (__ldg(&dec[box * 3]) > 0 ? 1 : 0) |
                   (__ldg(&dec[box * 3 + 1]) > 0 ? 2 : 0) |
                   (__ldg(&dec[box * 3 + 2]) > 0 ? 4 : 0);
        s_b[tid] = box >> 4;
    }
    __syncthreads();

    int j = tid / 3;
    int c = tid - 3 * j;

    float acc_nr = 0.f;
    float acc_rt = 0.f;
#pragma unroll 8
    for (int k = 0; k < NBG; ++k) {
        int d = s_d[k];
        size_t base = (size_t)s_b[k] * (HW * HW * 3);
        if (d & 1) {
            int row = s_y[k] + ((d & 4) ? r : (PB - 1 - r));
            int col = s_x[k] + ((d & 2) ? (PB - 1 - j) : j);
            acc_rt += __ldg(&grads[base + ((size_t)row * HW + col) * 3 + c]);
        } else {
            int row = s_y[k] + ((d & 4) ? (PB - 1 - r) : r);
            int col = s_x[k] + ((d & 2) ? (PB - 1 - j) : j);
            acc_nr += __ldg(&grads[base + ((size_t)row * HW + col) * 3 + c]);
        }
    }
    g_nr[g][r][tid] = acc_nr;
    g_rt[g][r][tid] = acc_rt;

    __syncthreads();
    __threadfence();
    if (tid == 0) atomicAdd(&g_sync[1], 1);
}

// ---------------------------------------------------------------------------
// Role: fused copy + paste, 4 rows per block, two-phase batched access.
// Phase 1: resolve covering box per quad-pixel (pure ALU).
// Phase 2: issue all needed loads back-to-back (high MLP).
// Phase 3: compose + store. Fully-pasted quads never read the source.
// ---------------------------------------------------------------------------
__device__ void role_copy(int cb, const float* __restrict__ images,
                          const int* __restrict__ box_yx, const int* __restrict__ dec,
                          float* __restrict__ out) {
    int b = cb >> 8;                     // 256 blocks per image
    int ybase = (cb & 255) * ROWS_PER_CP;
    int tid = threadIdx.x;

    __shared__ unsigned s_mask[ROWS_PER_CP];
    __shared__ int s_x0[NPER];
    __shared__ int s_y0[NPER];
    __shared__ int s_d[NPER];

    if (tid < 32) {
        int y0 = 0, x0 = 0, dd = 0;
        if (tid < NPER) {
            int box = b * NPER + tid;
            y0 = __ldg(&box_yx[box * 2]);
            x0 = __ldg(&box_yx[box * 2 + 1]);
            dd = (__ldg(&dec[box * 3]) > 0 ? 1 : 0) |
                 (__ldg(&dec[box * 3 + 1]) > 0 ? 2 : 0) |
                 (__ldg(&dec[box * 3 + 2]) > 0 ? 4 : 0);
            s_x0[tid] = x0;
            s_y0[tid] = y0;
            s_d[tid] = dd;
        }
#pragma unroll
        for (int r = 0; r < ROWS_PER_CP; r++) {
            int cov = (tid < NPER) && ((unsigned)(ybase + r - y0) < (unsigned)PB);
            unsigned m = __ballot_sync(0xFFFFFFFFu, cov) & 0xFFFFu;
            if (tid == 0) s_mask[r] = m;
        }
    }
    __syncthreads();

    size_t base4 = ((size_t)(b * HW + ybase)) * (HW * 3 / 4);  // float4 index of first row
    const float4* src4 = (const float4*)images + base4;
    float4* dst4 = (float4*)out + base4;

    unsigned allmask = s_mask[0] | s_mask[1] | s_mask[2] | s_mask[3];

    if (allmask == 0) {
        float4 v[8];
#pragma unroll
        for (int k = 0; k < 8; k++) v[k] = __ldcs(&src4[(k >> 1) * 768 + (k & 1) * THREADS + tid]);
#pragma unroll
        for (int k = 0; k < 8; k++) __stcs(&dst4[(k >> 1) * 768 + (k & 1) * THREADS + tid], v[k]);
        return;
    }

    // need patch for some quads: wait for downsample completion (fast after wave 1)
    if (tid == 0) {
        volatile int* p = &g_sync[0];
        while (*p < DS_BLOCKS) __nanosleep(64);
    }
    __syncthreads();

    // Phase 1: resolve boxes per quad (two spanned pixels each)
    int boxa[8], boxb[8];
#pragma unroll
    for (int k = 0; k < 8; k++) {
        int row = k >> 1;
        int q = (k & 1) * THREADS + tid;
        int pa = (q * 4) / 3;
        int ba = -1, bb = -1;
        unsigned m = s_mask[row];
        while (m) {
            int n = 31 - __clz(m);
            m &= ~(1u << n);
            int x0 = s_x0[n];
            if (ba < 0 && (unsigned)(pa - x0) < (unsigned)PB) ba = n;
            if (bb < 0 && (unsigned)(pa + 1 - x0) < (unsigned)PB) bb = n;
            if (ba >= 0 && bb >= 0) break;
        }
        boxa[k] = ba; boxb[k] = bb;
    }

    // Phase 2: issue all needed source loads back-to-back (MLP)
    float4 v[8];
#pragma unroll
    for (int k = 0; k < 8; k++) {
        if (boxa[k] < 0 || boxb[k] < 0)   // any un-pasted element -> need source
            v[k] = __ldcs(&src4[(k >> 1) * 768 + (k & 1) * THREADS + tid]);
    }

    // Phase 3: compose + store
#pragma unroll
    for (int k = 0; k < 8; k++) {
        int row = k >> 1;
        int q = (k & 1) * THREADS + tid;
        int fo = q * 4;
        int pa = fo / 3;
        float* vf = (float*)&v[k];
        if (boxa[k] >= 0 || boxb[k] >= 0) {
            int yg = ybase + row;
#pragma unroll
            for (int e = 0; e < 4; e++) {
                int fe = fo + e;
                int px = fe / 3;
                int box = (px == pa) ? boxa[k] : boxb[k];
                if (box < 0) continue;
                int c = fe - 3 * px;
                int rx = px - s_x0[box];
                int ry = yg - s_y0[box];
                int d = s_d[box];
                int y2 = (d & 4) ? (PB - 1 - ry) : ry;
                int x1 = (d & 2) ? (PB - 1 - rx) : rx;
                int sy_ = (d & 1) ? x1 : y2;
                int sx_ = (d & 1) ? (PB - 1 - y2) : x1;
                vf[e] = g_small[(sy_ * PB + sx_) * 3 + c];
            }
        }
        __stcs(&dst4[(k >> 1) * 768 + (k & 1) * THREADS + tid], v[k]);
    }
}

// ---------------------------------------------------------------------------
// Role: reduce gather partials + bilinear upsample 128->256 + analytic TV grad.
// ---------------------------------------------------------------------------
__device__ __forceinline__ float acc_at(int y, int x, int c) {
    float s = 0.f;
#pragma unroll
    for (int g = 0; g < NGRP; g++) {
        s += g_nr[g][y][x * 3 + c];
        s += g_rt[g][x][y * 3 + c];
    }
    return s;
}

__device__ void role_final(int fb, const float* __restrict__ patch,
                           float* __restrict__ agg) {
    if (threadIdx.x == 0) {
        volatile int* p = &g_sync[1];
        while (*p < GT_BLOCKS) __nanosleep(64);
    }
    __syncthreads();

    int t = fb * THREADS + threadIdx.x;
    int c = t % 3;
    int j = (t / 3) % PHW;
    int i = t / (PHW * 3);

    int ky = i >> 1, y0, y1; float wy0, wy1;
    if (i & 1) { y0 = ky;             y1 = min(ky + 1, PB - 1); wy0 = 0.75f; wy1 = 0.25f; }
    else       { y0 = max(ky - 1, 0); y1 = ky;                  wy0 = 0.25f; wy1 = 0.75f; }
    int kx = j >> 1, x0, x1; float wx0, wx1;
    if (j & 1) { x0 = kx;             x1 = min(kx + 1, PB - 1); wx0 = 0.75f; wx1 = 0.25f; }
    else       { x0 = max(kx - 1, 0); x1 = kx;                  wx0 = 0.25f; wx1 = 0.75f; }

    float v = wy0 * (wx0 * acc_at(y0, x0, c) + wx1 * acc_at(y0, x1, c))
            + wy1 * (wx0 * acc_at(y1, x0, c) + wx1 * acc_at(y1, x1, c));

    float pij = __ldg(&patch[(i * PHW + j) * 3 + c]);
    float a = (j < PHW - 1) ? (pij - __ldg(&patch[(i * PHW + j + 1) * 3 + c])) : 0.f;
    float bb = (i < PHW - 1) ? (pij - __ldg(&patch[((i + 1) * PHW + j) * 3 + c])) : 0.f;
    float g = (a + bb) * rsqrtf(a * a + bb * bb + 1e-12f);
    if (j > 0) {
        float pl = __ldg(&patch[(i * PHW + j - 1) * 3 + c]);
        float al = pl - pij;
        float bl = (i < PHW - 1) ? (pl - __ldg(&patch[((i + 1) * PHW + j - 1) * 3 + c])) : 0.f;
        g -= al * rsqrtf(al * al + bl * bl + 1e-12f);
    }
    if (i > 0) {
        float pu = __ldg(&patch[((i - 1) * PHW + j) * 3 + c]);
        float bu = pu - pij;
        float au = (j < PHW - 1) ? (pu - __ldg(&patch[((i - 1) * PHW + j + 1) * 3 + c])) : 0.f;
        g -= bu * rsqrtf(au * au + bu * bu + 1e-12f);
    }
    agg[t] = v + 0.5f * g;
}

// ---------------------------------------------------------------------------
__global__ void __launch_bounds__(THREADS) k_mega(
        const float* __restrict__ images, const float* __restrict__ grads,
        const float* __restrict__ patch,
        const int* __restrict__ box_yx, const int* __restrict__ dec,
        float* __restrict__ out, float* __restrict__ agg) {
    int bid = blockIdx.x;
    if (bid < DS_BLOCKS) {
        role_downsample(bid, patch);
    } else if (bid < DS_BLOCKS + GT_BLOCKS) {
        role_gather(bid - DS_BLOCKS, grads, box_yx, dec);
    } else if (bid < DS_BLOCKS + GT_BLOCKS + CP_BLOCKS) {
        role_copy(bid - (DS_BLOCKS + GT_BLOCKS), images, box_yx, dec, out);
    } else {
        role_final(bid - (DS_BLOCKS + GT_BLOCKS + CP_BLOCKS), patch, agg);
    }
}

// ---------------------------------------------------------------------------
extern "C" void kernel_launch(void* const* d_in, const int* in_sizes, int n_in,
                              void* d_out, int out_size) {
    const float* images = (const float*)d_in[0];
    const float* grads  = (const float*)d_in[1];
    const float* patch  = (const float*)d_in[2];
    const int*   box_yx = (const int*)d_in[3];
    const int*   dec    = (const int*)d_in[4];

    float* out = (float*)d_out;
    size_t img_elems = (size_t)BIMG * HW * HW * 3;
    float* agg = out + img_elems;

    void* sptr = nullptr;
    cudaGetSymbolAddress(&sptr, g_sync);
    cudaMemsetAsync(sptr, 0, 2 * sizeof(int));

    k_mega<<<TOTAL_BLOCKS, THREADS>>>(images, grads, patch, box_yx, dec, out, agg);
}

// round 6
// speedup vs baseline: 2.0330x; 1.1030x over previous
#include <cuda_runtime.h>

#define PB   128
#define PHW  256
#define HW   1024
#define BIMG 8
#define NPER 16
#define NB   128
#define NGRP 4
#define NBG  (NB / NGRP)          // 32 boxes per gather group

#define THREADS    384
#define DS_BLOCKS  128            // 128*384 = 49152 = PB*PB*3
#define GT_BLOCKS  (NGRP * PB)    // 512
#define ROWS_PER_CP 4
#define CP_BLOCKS  (BIMG * HW / ROWS_PER_CP)   // 2048
#define FN_BLOCKS  512            // 512*384 = 196608 = PHW*PHW*3
#define TOTAL_BLOCKS (DS_BLOCKS + GT_BLOCKS + CP_BLOCKS + FN_BLOCKS)

// sign-extend low 8 bits (aarch64 'char' is unsigned — never use bare char!)
#define SEXT8(x) (((int)((x) << 24)) >> 24)

// Scratch (device globals — no allocation allowed)
__device__ float g_small[PB * PB * 3];              // downsampled patch
__device__ float g_nr[NGRP][PB][PB * 3];            // non-rot gather partials
__device__ float g_rt[NGRP][PB][PB * 3];            // rot gather partials (transposed)
__device__ int   g_sync[2];                          // [0]=ds done, [1]=gather done

// ---------------------------------------------------------------------------
// Role: antialiased bilinear downsample 256->128 (JAX triangle taps
// {0.25,0.75,0.75,0.25}, per-dim edge renormalization).
// ---------------------------------------------------------------------------
__device__ void role_downsample(int bid, const float* __restrict__ patch) {
    int t = bid * THREADS + threadIdx.x;
    int c = t % 3;
    int j = (t / 3) % PB;
    int i = t / (3 * PB);

    const float w0[4] = {0.25f, 0.75f, 0.75f, 0.25f};
    int by = 2 * i - 1, bx = 2 * j - 1;
    float wy[4], wx[4], sy = 0.f, sx = 0.f;
#pragma unroll
    for (int u = 0; u < 4; u++) { int r = by + u; wy[u] = (r >= 0 && r < PHW) ? w0[u] : 0.f; sy += wy[u]; }
#pragma unroll
    for (int v = 0; v < 4; v++) { int q = bx + v; wx[v] = (q >= 0 && q < PHW) ? w0[v] : 0.f; sx += wx[v]; }

    float acc = 0.f;
#pragma unroll
    for (int u = 0; u < 4; u++) {
        if (wy[u] == 0.f) continue;
        int r = by + u;
        float rowacc = 0.f;
#pragma unroll
        for (int v = 0; v < 4; v++) {
            if (wx[v] == 0.f) continue;
            rowacc += wx[v] * __ldg(&patch[(r * PHW + (bx + v)) * 3 + c]);
        }
        acc += wy[u] * rowacc;
    }
    g_small[t] = acc / (sy * sx);

    __syncthreads();
    __threadfence();
    if (threadIdx.x == 0) atomicAdd(&g_sync[0], 1);
}

// ---------------------------------------------------------------------------
// Role: gradient gather + inverse transform (coalesced for rot and non-rot).
// ---------------------------------------------------------------------------
__device__ void role_gather(int gb, const float* __restrict__ grads,
                            const int* __restrict__ box_yx,
                            const int* __restrict__ dec) {
    __shared__ int s_y[NBG], s_x[NBG], s_d[NBG], s_b[NBG];
    int tid = threadIdx.x;
    int g = gb >> 7;
    int r = gb & 127;

    if (tid < NBG) {
        int box = g * NBG + tid;
        s_y[tid] = __ldg(&box_yx[box * 2]);
        s_x[tid] = __ldg(&box_yx[box * 2 + 1]);
        s_d[tid] = (__ldg(&dec[box * 3]) > 0 ? 1 : 0) |
                   (__ldg(&dec[box * 3 + 1]) > 0 ? 2 : 0) |
                   (__ldg(&dec[box * 3 + 2]) > 0 ? 4 : 0);
        s_b[tid] = box >> 4;
    }
    __syncthreads();

    int j = tid / 3;
    int c = tid - 3 * j;

    float acc_nr = 0.f;
    float acc_rt = 0.f;
#pragma unroll 8
    for (int k = 0; k < NBG; ++k) {
        int d = s_d[k];
        size_t base = (size_t)s_b[k] * (HW * HW * 3);
        if (d & 1) {
            int row = s_y[k] + ((d & 4) ? r : (PB - 1 - r));
            int col = s_x[k] + ((d & 2) ? (PB - 1 - j) : j);
            acc_rt += __ldg(&grads[base + ((size_t)row * HW + col) * 3 + c]);
        } else {
            int row = s_y[k] + ((d & 4) ? (PB - 1 - r) : r);
            int col = s_x[k] + ((d & 2) ? (PB - 1 - j) : j);
            acc_nr += __ldg(&grads[base + ((size_t)row * HW + col) * 3 + c]);
        }
    }
    g_nr[g][r][tid] = acc_nr;
    g_rt[g][r][tid] = acc_rt;

    __syncthreads();
    __threadfence();
    if (tid == 0) atomicAdd(&g_sync[1], 1);
}

// ---------------------------------------------------------------------------
// Role: fused copy + paste, 4 rows per block, chunked (4 quads at a time) to
// keep live registers low (occupancy!) while retaining MLP=4.
// ---------------------------------------------------------------------------
__device__ void role_copy(int cb, const float* __restrict__ images,
                          const int* __restrict__ box_yx, const int* __restrict__ dec,
                          float* __restrict__ out) {
    int b = cb >> 8;                     // 256 blocks per image
    int ybase = (cb & 255) * ROWS_PER_CP;
    int tid = threadIdx.x;

    __shared__ unsigned s_mask[ROWS_PER_CP];
    __shared__ int s_x0[NPER];
    __shared__ int s_y0[NPER];
    __shared__ int s_d[NPER];

    if (tid < 32) {
        int y0 = 0;
        if (tid < NPER) {
            int box = b * NPER + tid;
            y0 = __ldg(&box_yx[box * 2]);
            s_x0[tid] = __ldg(&box_yx[box * 2 + 1]);
            s_y0[tid] = y0;
            s_d[tid] = (__ldg(&dec[box * 3]) > 0 ? 1 : 0) |
                       (__ldg(&dec[box * 3 + 1]) > 0 ? 2 : 0) |
                       (__ldg(&dec[box * 3 + 2]) > 0 ? 4 : 0);
        }
#pragma unroll
        for (int r = 0; r < ROWS_PER_CP; r++) {
            int cov = (tid < NPER) && ((unsigned)(ybase + r - y0) < (unsigned)PB);
            unsigned m = __ballot_sync(0xFFFFFFFFu, cov) & 0xFFFFu;
            if (tid == 0) s_mask[r] = m;
        }
    }
    __syncthreads();

    size_t base4 = ((size_t)(b * HW + ybase)) * (HW * 3 / 4);
    const float4* src4 = (const float4*)images + base4;
    float4* dst4 = (float4*)out + base4;

    unsigned allmask = s_mask[0] | s_mask[1] | s_mask[2] | s_mask[3];

    if (allmask == 0) {
        // pure copy: two chunks of 4 float4 (MLP=4, low live regs)
#pragma unroll
        for (int h = 0; h < 2; h++) {
            float4 v[4];
#pragma unroll
            for (int k = 0; k < 4; k++) {
                int q = (h * 4 + k);
                v[k] = __ldcs(&src4[(q >> 1) * 768 + (q & 1) * THREADS + tid]);
            }
#pragma unroll
            for (int k = 0; k < 4; k++) {
                int q = (h * 4 + k);
                __stcs(&dst4[(q >> 1) * 768 + (q & 1) * THREADS + tid], v[k]);
            }
        }
        return;
    }

    // need patch: wait for downsample completion (fast after wave 1)
    if (tid == 0) {
        volatile int* p = &g_sync[0];
        while (*p < DS_BLOCKS) __nanosleep(64);
    }
    __syncthreads();

#pragma unroll
    for (int h = 0; h < 2; h++) {
        // Phase 1: resolve covering boxes for 4 quads (packed: ba | bb<<8)
        int pk[4];
#pragma unroll
        for (int k = 0; k < 4; k++) {
            int q = h * 4 + k;
            int row = q >> 1;
            int qq = (q & 1) * THREADS + tid;
            int pa = (qq * 4) / 3;
            int ba = -1, bb = -1;
            unsigned m = s_mask[row];
            while (m) {
                int n = 31 - __clz(m);
                m &= ~(1u << n);
                int x0 = s_x0[n];
                if (ba < 0 && (unsigned)(pa - x0) < (unsigned)PB) ba = n;
                if (bb < 0 && (unsigned)(pa + 1 - x0) < (unsigned)PB) bb = n;
                if (ba >= 0 && bb >= 0) break;
            }
            pk[k] = (ba & 0xFF) | ((bb & 0xFF) << 8);
        }

        // Phase 2: batched source loads (skip fully-pasted quads)
        float4 v[4];
#pragma unroll
        for (int k = 0; k < 4; k++) {
            int q = h * 4 + k;
            int ba = SEXT8(pk[k] & 0xFF);
            int bb = SEXT8((pk[k] >> 8) & 0xFF);
            if (ba < 0 || bb < 0)
                v[k] = __ldcs(&src4[(q >> 1) * 768 + (q & 1) * THREADS + tid]);
        }

        // Phase 3: compose + store
#pragma unroll
        for (int k = 0; k < 4; k++) {
            int q = h * 4 + k;
            int row = q >> 1;
            int qq = (q & 1) * THREADS + tid;
            int fo = qq * 4;
            int pa = fo / 3;
            int ba = SEXT8(pk[k] & 0xFF);
            int bb = SEXT8((pk[k] >> 8) & 0xFF);
            float* vf = (float*)&v[k];
            if (ba >= 0 || bb >= 0) {
                int yg = ybase + row;
#pragma unroll
                for (int e = 0; e < 4; e++) {
                    int fe = fo + e;
                    int px = fe / 3;
                    int box = (px == pa) ? ba : bb;
                    if (box < 0) continue;
                    int c = fe - 3 * px;
                    int rx = px - s_x0[box];
                    int ry = yg - s_y0[box];
                    int d = s_d[box];
                    int y2 = (d & 4) ? (PB - 1 - ry) : ry;
                    int x1 = (d & 2) ? (PB - 1 - rx) : rx;
                    int sy_ = (d & 1) ? x1 : y2;
                    int sx_ = (d & 1) ? (PB - 1 - y2) : x1;
                    vf[e] = g_small[(sy_ * PB + sx_) * 3 + c];
                }
            }
            __stcs(&dst4[(q >> 1) * 768 + (q & 1) * THREADS + tid], v[k]);
        }
    }
}

// ---------------------------------------------------------------------------
// Role: reduce gather partials + bilinear upsample 128->256 + analytic TV grad.
// ---------------------------------------------------------------------------
__device__ __forceinline__ float acc_at(int y, int x, int c) {
    float s = 0.f;
#pragma unroll
    for (int g = 0; g < NGRP; g++) {
        s += g_nr[g][y][x * 3 + c];
        s += g_rt[g][x][y * 3 + c];
    }
    return s;
}

__device__ void role_final(int fb, const float* __restrict__ patch,
                           float* __restrict__ agg) {
    if (threadIdx.x == 0) {
        volatile int* p = &g_sync[1];
        while (*p < GT_BLOCKS) __nanosleep(64);
    }
    __syncthreads();

    int t = fb * THREADS + threadIdx.x;
    int c = t % 3;
    int j = (t / 3) % PHW;
    int i = t / (PHW * 3);

    int ky = i >> 1, y0, y1; float wy0, wy1;
    if (i & 1) { y0 = ky;             y1 = min(ky + 1, PB - 1); wy0 = 0.75f; wy1 = 0.25f; }
    else       { y0 = max(ky - 1, 0); y1 = ky;                  wy0 = 0.25f; wy1 = 0.75f; }
    int kx = j >> 1, x0, x1; float wx0, wx1;
    if (j & 1) { x0 = kx;             x1 = min(kx + 1, PB - 1); wx0 = 0.75f; wx1 = 0.25f; }
    else       { x0 = max(kx - 1, 0); x1 = kx;                  wx0 = 0.25f; wx1 = 0.75f; }

    float v = wy0 * (wx0 * acc_at(y0, x0, c) + wx1 * acc_at(y0, x1, c))
            + wy1 * (wx0 * acc_at(y1, x0, c) + wx1 * acc_at(y1, x1, c));

    float pij = __ldg(&patch[(i * PHW + j) * 3 + c]);
    float a = (j < PHW - 1) ? (pij - __ldg(&patch[(i * PHW + j + 1) * 3 + c])) : 0.f;
    float bb = (i < PHW - 1) ? (pij - __ldg(&patch[((i + 1) * PHW + j) * 3 + c])) : 0.f;
    float g = (a + bb) * rsqrtf(a * a + bb * bb + 1e-12f);
    if (j > 0) {
        float pl = __ldg(&patch[(i * PHW + j - 1) * 3 + c]);
        float al = pl - pij;
        float bl = (i < PHW - 1) ? (pl - __ldg(&patch[((i + 1) * PHW + j - 1) * 3 + c])) : 0.f;
        g -= al * rsqrtf(al * al + bl * bl + 1e-12f);
    }
    if (i > 0) {
        float pu = __ldg(&patch[((i - 1) * PHW + j) * 3 + c]);
        float bu = pu - pij;
        float au = (j < PHW - 1) ? (pu - __ldg(&patch[((i - 1) * PHW + j + 1) * 3 + c])) : 0.f;
        g -= bu * rsqrtf(au * au + bu * bu + 1e-12f);
    }
    agg[t] = v + 0.5f * g;
}

// ---------------------------------------------------------------------------
__global__ void __launch_bounds__(THREADS, 4) k_mega(
        const float* __restrict__ images, const float* __restrict__ grads,
        const float* __restrict__ patch,
        const int* __restrict__ box_yx, const int* __restrict__ dec,
        float* __restrict__ out, float* __restrict__ agg) {
    int bid = blockIdx.x;
    if (bid < DS_BLOCKS) {
        role_downsample(bid, patch);
    } else if (bid < DS_BLOCKS + GT_BLOCKS) {
        role_gather(bid - DS_BLOCKS, grads, box_yx, dec);
    } else if (bid < DS_BLOCKS + GT_BLOCKS + CP_BLOCKS) {
        role_copy(bid - (DS_BLOCKS + GT_BLOCKS), images, box_yx, dec, out);
    } else {
        role_final(bid - (DS_BLOCKS + GT_BLOCKS + CP_BLOCKS), patch, agg);
    }
}

// ---------------------------------------------------------------------------
extern "C" void kernel_launch(void* const* d_in, const int* in_sizes, int n_in,
                              void* d_out, int out_size) {
    const float* images = (const float*)d_in[0];
    const float* grads  = (const float*)d_in[1];
    const float* patch  = (const float*)d_in[2];
    const int*   box_yx = (const int*)d_in[3];
    const int*   dec    = (const int*)d_in[4];

    float* out = (float*)d_out;
    size_t img_elems = (size_t)BIMG * HW * HW * 3;
    float* agg = out + img_elems;

    void* sptr = nullptr;
    cudaGetSymbolAddress(&sptr, g_sync);
    cudaMemsetAsync(sptr, 0, 2 * sizeof(int));

    k_mega<<<TOTAL_BLOCKS, THREADS>>>(images, grads, patch, box_yx, dec, out, agg);
}